// round 1
// baseline (speedup 1.0000x reference)
#include <cuda_runtime.h>
#include <cuda_bf16.h>

#define B_ROWS    16384
#define KDIM      192
#define CDIM      256
#define TILE_ROWS 32
#define NTILES    (B_ROWS / TILE_ROWS)
#define GEMM_GRID 148
#define SMEM_BYTES ((KDIM*CDIM + TILE_ROWS*CDIM) * 4)   // 229376

// Scratch: pooled/concatenated features [B_ROWS][KDIM]
__device__ float g_X[B_ROWS * KDIM];

// ---- packed fp32x2 helpers (Blackwell PTX-only FFMA2) ----
__device__ __forceinline__ double ffma2(double a, double b, double c) {
    double d;
    asm("fma.rn.f32x2 %0, %1, %2, %3;" : "=d"(d) : "d"(b), "d"(c), "d"(a));
    return d;
}
__device__ __forceinline__ double pack2(float x) {
    double d;
    asm("mov.b64 %0, {%1, %1};" : "=d"(d) : "f"(x));
    return d;
}
__device__ __forceinline__ void unpack2(double d, float& lo, float& hi) {
    asm("mov.b64 {%0, %1}, %2;" : "=f"(lo), "=f"(hi) : "d"(d));
}

// ============================================================
// Kernel A: gather + mean-pool -> g_X[row][0:192]
//   one warp per row
// ============================================================
__global__ void __launch_bounds__(256) gather_kernel(
    const int*   __restrict__ user_input,
    const float* __restrict__ emb,
    const int*   __restrict__ sc_country_idx,
    const float* __restrict__ sc_country_emb,
    const int*   __restrict__ sc_device_idx,
    const float* __restrict__ sc_device_emb,
    const int*   __restrict__ mf_tags_idx,
    const float* __restrict__ mf_tags_emb,
    const int*   __restrict__ mf_history_idx,
    const float* __restrict__ mf_history_emb)
{
    int row  = (blockIdx.x * blockDim.x + threadIdx.x) >> 5;
    int lane = threadIdx.x & 31;
    if (row >= B_ROWS) return;

    int u = user_input[row];
    float* xg = g_X + (size_t)row * KDIM;

    // main embedding: 64 floats
    float2 e = ((const float2*)(emb + (size_t)u * 64))[lane];
    ((float2*)xg)[lane] = e;

    // scalar side features
    int ci = sc_country_idx[u];
    int di = sc_device_idx[u];
    xg[64 + lane] = sc_country_emb[(size_t)ci * 32 + lane];
    xg[96 + lane] = sc_device_emb[(size_t)di * 32 + lane];

    // tags: mean over 20
    int ti = (lane < 20) ? mf_tags_idx[(size_t)u * 20 + lane] : 0;
    float tacc = 0.f;
    #pragma unroll
    for (int t = 0; t < 20; t++) {
        int id = __shfl_sync(0xffffffffu, ti, t);
        tacc += mf_tags_emb[(size_t)id * 32 + lane];
    }
    xg[128 + lane] = tacc * (1.f / 20.f);

    // history: mean over 50
    int hA = mf_history_idx[(size_t)u * 50 + lane];
    int hB = (lane < 18) ? mf_history_idx[(size_t)u * 50 + 32 + lane] : 0;
    float a0 = 0.f, a1 = 0.f;
    #pragma unroll
    for (int t = 0; t < 32; t++) {
        int id = __shfl_sync(0xffffffffu, hA, t);
        a0 += mf_history_emb[(size_t)id * 32 + lane];
    }
    #pragma unroll
    for (int t = 0; t < 18; t++) {
        int id = __shfl_sync(0xffffffffu, hB, t);
        a1 += mf_history_emb[(size_t)id * 32 + lane];
    }
    xg[160 + lane] = (a0 + a1) * (1.f / 50.f);
}

// ============================================================
// Kernel B: y = LN(relu(X @ W^T + b))
//   persistent blocks; full W (k-major) in smem; 32-row tiles
//   thread = (rowgroup of 8 rows) x (4 channels as 2 f32x2 pairs)
// ============================================================
__global__ void __launch_bounds__(256, 1) gemm_ln_kernel(
    const float* __restrict__ fc_w,   // [256][192]
    const float* __restrict__ fc_b,   // [256]
    const float* __restrict__ ln_g,
    const float* __restrict__ ln_b,
    float*       __restrict__ out)    // [B_ROWS][256]
{
    extern __shared__ float sm[];
    float* sW = sm;                    // [192][256] k-major (transposed fc_w)
    float* sX = sm + KDIM * CDIM;      // [32][192], reused as ys[32][256]

    int tid = threadIdx.x;

    // load + transpose W into smem (coalesced global reads)
    for (int i = tid; i < KDIM * CDIM; i += 256) {
        int ch = i / KDIM;
        int k  = i - ch * KDIM;
        sW[k * CDIM + ch] = fc_w[i];
    }

    int lane = tid & 31;
    int warp = tid >> 5;
    int rg   = warp & 3;        // rowgroup: rows rg*8 .. rg*8+7
    int h    = warp >> 2;       // channel half: 0 or 1
    int p0   = h * 64 + lane;   // channel-pair index (channels 2p0, 2p0+1)
    int p1   = p0 + 32;

    float b00 = fc_b[2*p0], b01 = fc_b[2*p0+1];
    float b10 = fc_b[2*p1], b11 = fc_b[2*p1+1];

    // LN params for epilogue mapping (channels lane + 32*j)
    float gg[8], bb[8];
    #pragma unroll
    for (int j = 0; j < 8; j++) {
        gg[j] = ln_g[lane + 32*j];
        bb[j] = ln_b[lane + 32*j];
    }

    for (int tile = blockIdx.x; tile < NTILES; tile += gridDim.x) {
        __syncthreads();   // W ready (first iter) / previous LN reads done

        // load X tile [32][192] (float4 coalesced)
        const float4* xsrc = (const float4*)(g_X + (size_t)tile * TILE_ROWS * KDIM);
        float4* xdst = (float4*)sX;
        #pragma unroll
        for (int i = 0; i < (TILE_ROWS * KDIM / 4) / 256; i++)   // 6 iters
            xdst[tid + i * 256] = xsrc[tid + i * 256];
        __syncthreads();

        double acc0[8], acc1[8];
        #pragma unroll
        for (int r = 0; r < 8; r++) { acc0[r] = 0.0; acc1[r] = 0.0; }

        const float* xrow = sX + rg * 8 * KDIM;
        #pragma unroll 2
        for (int k0 = 0; k0 < KDIM; k0 += 4) {
            float4 xr[8];
            #pragma unroll
            for (int r = 0; r < 8; r++)
                xr[r] = *(const float4*)&xrow[r * KDIM + k0];
            #pragma unroll
            for (int kk = 0; kk < 4; kk++) {
                const float* wrow = &sW[(k0 + kk) * CDIM];
                double w0 = *(const double*)&wrow[2*p0];
                double w1 = *(const double*)&wrow[2*p1];
                #pragma unroll
                for (int r = 0; r < 8; r++) {
                    float xv = (kk == 0) ? xr[r].x : (kk == 1) ? xr[r].y
                             : (kk == 2) ? xr[r].z : xr[r].w;
                    double xx = pack2(xv);
                    acc0[r] = ffma2(acc0[r], w0, xx);
                    acc1[r] = ffma2(acc1[r], w1, xx);
                }
            }
        }
        __syncthreads();   // sX reads done before ys overwrite (shared region)

        // bias + relu -> ys [32][256]
        float* ys = sX;
        #pragma unroll
        for (int r = 0; r < 8; r++) {
            float2* yrow = (float2*)&ys[(rg * 8 + r) * CDIM];
            float lo, hi;
            unpack2(acc0[r], lo, hi);
            yrow[p0] = make_float2(fmaxf(lo + b00, 0.f), fmaxf(hi + b01, 0.f));
            unpack2(acc1[r], lo, hi);
            yrow[p1] = make_float2(fmaxf(lo + b10, 0.f), fmaxf(hi + b11, 0.f));
        }
        __syncthreads();

        // LayerNorm: warp handles rows warp*4 .. warp*4+3
        #pragma unroll
        for (int rr = 0; rr < 4; rr++) {
            int row = warp * 4 + rr;
            float v[8];
            float sum = 0.f, ss = 0.f;
            #pragma unroll
            for (int j = 0; j < 8; j++) {
                v[j] = ys[row * CDIM + lane + 32*j];
                sum += v[j];
                ss  += v[j] * v[j];
            }
            #pragma unroll
            for (int o = 16; o; o >>= 1) {
                sum += __shfl_xor_sync(0xffffffffu, sum, o);
                ss  += __shfl_xor_sync(0xffffffffu, ss,  o);
            }
            float mean = sum * (1.f / 256.f);
            float var  = ss * (1.f / 256.f) - mean * mean;
            float rstd = rsqrtf(var + 1e-5f);
            float* orow = out + ((size_t)tile * TILE_ROWS + row) * CDIM;
            #pragma unroll
            for (int j = 0; j < 8; j++)
                orow[lane + 32*j] = (v[j] - mean) * rstd * gg[j] + bb[j];
        }
    }
}

// ============================================================
extern "C" void kernel_launch(void* const* d_in, const int* in_sizes, int n_in,
                              void* d_out, int out_size) {
    (void)in_sizes; (void)n_in; (void)out_size;
    const int*   user_input      = (const int*)  d_in[0];
    const float* emb             = (const float*)d_in[1];
    const int*   sc_country_idx  = (const int*)  d_in[2];
    const float* sc_country_emb  = (const float*)d_in[3];
    const int*   sc_device_idx   = (const int*)  d_in[4];
    const float* sc_device_emb   = (const float*)d_in[5];
    const int*   mf_tags_idx     = (const int*)  d_in[6];
    const float* mf_tags_emb     = (const float*)d_in[7];
    const int*   mf_history_idx  = (const int*)  d_in[8];
    const float* mf_history_emb  = (const float*)d_in[9];
    const float* fc_w            = (const float*)d_in[10];
    const float* fc_b            = (const float*)d_in[11];
    const float* ln_g            = (const float*)d_in[12];
    const float* ln_b            = (const float*)d_in[13];
    float* out = (float*)d_out;

    gather_kernel<<<B_ROWS / 8, 256>>>(
        user_input, emb,
        sc_country_idx, sc_country_emb,
        sc_device_idx,  sc_device_emb,
        mf_tags_idx,    mf_tags_emb,
        mf_history_idx, mf_history_emb);

    cudaFuncSetAttribute(gemm_ln_kernel,
                         cudaFuncAttributeMaxDynamicSharedMemorySize, SMEM_BYTES);
    gemm_ln_kernel<<<GEMM_GRID, 256, SMEM_BYTES>>>(fc_w, fc_b, ln_g, ln_b, out);
}

// round 2
// speedup vs baseline: 1.1860x; 1.1860x over previous
#include <cuda_runtime.h>
#include <cuda_bf16.h>

#define B_ROWS    16384
#define KDIM      192
#define CDIM      256
#define TILE_ROWS 32
#define NTILES    (B_ROWS / TILE_ROWS)
#define GEMM_GRID 148
#define GEMM_THREADS 512
// smem: sW2 (96*256 doubles = 196608B) + ys/sX region (32*256*4 = 32768B)
#define SW2_BYTES 196608
#define SMEM_BYTES (SW2_BYTES + TILE_ROWS*CDIM*4)   // 229376

// Scratch: pooled/concatenated features [B_ROWS][KDIM]
__device__ float g_X[B_ROWS * KDIM];

// ---- packed fp32x2 helpers (Blackwell PTX-only FFMA2) ----
__device__ __forceinline__ double ffma2(double a, double b, double c) {
    double d;
    asm("fma.rn.f32x2 %0, %1, %2, %3;" : "=d"(d) : "d"(b), "d"(c), "d"(a));
    return d;
}
__device__ __forceinline__ double packd(float lo, float hi) {
    double d;
    asm("mov.b64 %0, {%1, %2};" : "=d"(d) : "f"(lo), "f"(hi));
    return d;
}
__device__ __forceinline__ void unpack2(double d, float& lo, float& hi) {
    asm("mov.b64 {%0, %1}, %2;" : "=f"(lo), "=f"(hi) : "d"(d));
}

// ============================================================
// Kernel A: gather + mean-pool -> g_X[row][0:192]
//   one warp per row
// ============================================================
__global__ void __launch_bounds__(256) gather_kernel(
    const int*   __restrict__ user_input,
    const float* __restrict__ emb,
    const int*   __restrict__ sc_country_idx,
    const float* __restrict__ sc_country_emb,
    const int*   __restrict__ sc_device_idx,
    const float* __restrict__ sc_device_emb,
    const int*   __restrict__ mf_tags_idx,
    const float* __restrict__ mf_tags_emb,
    const int*   __restrict__ mf_history_idx,
    const float* __restrict__ mf_history_emb)
{
    int row  = (blockIdx.x * blockDim.x + threadIdx.x) >> 5;
    int lane = threadIdx.x & 31;
    if (row >= B_ROWS) return;

    int u = user_input[row];
    float* xg = g_X + (size_t)row * KDIM;

    // main embedding: 64 floats
    float2 e = ((const float2*)(emb + (size_t)u * 64))[lane];
    ((float2*)xg)[lane] = e;

    // scalar side features
    int ci = sc_country_idx[u];
    int di = sc_device_idx[u];
    xg[64 + lane] = sc_country_emb[(size_t)ci * 32 + lane];
    xg[96 + lane] = sc_device_emb[(size_t)di * 32 + lane];

    // tags: mean over 20
    int ti = (lane < 20) ? mf_tags_idx[(size_t)u * 20 + lane] : 0;
    float tacc = 0.f;
    #pragma unroll
    for (int t = 0; t < 20; t++) {
        int id = __shfl_sync(0xffffffffu, ti, t);
        tacc += mf_tags_emb[(size_t)id * 32 + lane];
    }
    xg[128 + lane] = tacc * (1.f / 20.f);

    // history: mean over 50
    int hA = mf_history_idx[(size_t)u * 50 + lane];
    int hB = (lane < 18) ? mf_history_idx[(size_t)u * 50 + 32 + lane] : 0;
    float a0 = 0.f, a1 = 0.f;
    #pragma unroll
    for (int t = 0; t < 32; t++) {
        int id = __shfl_sync(0xffffffffu, hA, t);
        a0 += mf_history_emb[(size_t)id * 32 + lane];
    }
    #pragma unroll
    for (int t = 0; t < 18; t++) {
        int id = __shfl_sync(0xffffffffu, hB, t);
        a1 += mf_history_emb[(size_t)id * 32 + lane];
    }
    xg[160 + lane] = (a0 + a1) * (1.f / 50.f);
}

// ============================================================
// Kernel B: y = LN(relu(X @ W^T + b))
//   512 threads, persistent blocks; W packed as k-pair doubles:
//   sW2[kp][c] = (W[c][2kp], W[c][2kp+1]).
//   Accumulator doubles hold (even-k sum, odd-k sum); folded at end.
//   Thread = 8 rows x 2 adjacent channels.
// ============================================================
__global__ void __launch_bounds__(GEMM_THREADS, 1) gemm_ln_kernel(
    const float* __restrict__ fc_w,   // [256][192]
    const float* __restrict__ fc_b,   // [256]
    const float* __restrict__ ln_g,
    const float* __restrict__ ln_b,
    float*       __restrict__ out)    // [B_ROWS][256]
{
    extern __shared__ char smraw[];
    double* sW2 = (double*)smraw;                 // [96][256]
    float*  sX  = (float*)(smraw + SW2_BYTES);    // [32][192], reused as ys[32][256]

    int tid = threadIdx.x;

    // load W, repack as k-pair doubles (coalesced-ish float4 reads)
    {
        const float4* w4 = (const float4*)fc_w;
        for (int i = tid; i < CDIM * (KDIM / 4); i += GEMM_THREADS) {
            int q = i >> 8;         // 0..47 : which float4 along k
            int c = i & 255;        // channel
            float4 v = w4[c * (KDIM / 4) + q];
            sW2[(2 * q) * CDIM + c]     = packd(v.x, v.y);
            sW2[(2 * q + 1) * CDIM + c] = packd(v.z, v.w);
        }
    }

    int lane = tid & 31;
    int warp = tid >> 5;
    int rg   = warp & 3;            // rowgroup: rows rg*8 .. rg*8+7
    int h    = warp >> 2;           // channel quarter: 0..3
    int c0   = h * 64 + lane * 2;   // channels c0, c0+1

    float bias0 = fc_b[c0];
    float bias1 = fc_b[c0 + 1];

    // LN params (channels lane + 32*j)
    float gg[8], bb[8];
    #pragma unroll
    for (int j = 0; j < 8; j++) {
        gg[j] = ln_g[lane + 32 * j];
        bb[j] = ln_b[lane + 32 * j];
    }

    for (int tile = blockIdx.x; tile < NTILES; tile += gridDim.x) {
        __syncthreads();   // W ready (first iter) / previous LN reads done

        // load X tile [32][192] (float4 coalesced): 1536 float4 / 512 = 3 each
        {
            const float4* xsrc = (const float4*)(g_X + (size_t)tile * TILE_ROWS * KDIM);
            float4* xdst = (float4*)sX;
            #pragma unroll
            for (int i = 0; i < (TILE_ROWS * KDIM / 4) / GEMM_THREADS; i++)
                xdst[tid + i * GEMM_THREADS] = xsrc[tid + i * GEMM_THREADS];
        }
        __syncthreads();

        double acc0[8], acc1[8];   // [row] x {channel c0, c0+1}
        #pragma unroll
        for (int r = 0; r < 8; r++) { acc0[r] = 0.0; acc1[r] = 0.0; }

        const float* xrow = sX + rg * 8 * KDIM;
        #pragma unroll 2
        for (int kb = 0; kb < KDIM; kb += 4) {
            int kp = kb >> 1;
            // w for the two k-pairs, both channels: two LDS.128
            double2 w0 = *(const double2*)&sW2[kp * CDIM + c0];        // k-pair kp
            double2 w1 = *(const double2*)&sW2[(kp + 1) * CDIM + c0];  // k-pair kp+1
            #pragma unroll
            for (int r = 0; r < 8; r++) {
                // x[r][kb..kb+3] as two packed k-pair doubles (bit reinterpret)
                double2 xd = *(const double2*)&xrow[r * KDIM + kb];
                acc0[r] = ffma2(acc0[r], w0.x, xd.x);
                acc1[r] = ffma2(acc1[r], w0.y, xd.x);
                acc0[r] = ffma2(acc0[r], w1.x, xd.y);
                acc1[r] = ffma2(acc1[r], w1.y, xd.y);
            }
        }
        __syncthreads();   // all sX reads done before ys overwrite (shared region)

        // fold k-pair halves, bias + relu -> ys [32][256]
        float* ys = sX;
        #pragma unroll
        for (int r = 0; r < 8; r++) {
            float lo, hi, y0, y1;
            unpack2(acc0[r], lo, hi);
            y0 = fmaxf(lo + hi + bias0, 0.f);
            unpack2(acc1[r], lo, hi);
            y1 = fmaxf(lo + hi + bias1, 0.f);
            *(float2*)&ys[(rg * 8 + r) * CDIM + c0] = make_float2(y0, y1);
        }
        __syncthreads();

        // LayerNorm: warp handles rows warp*2 .. warp*2+1
        #pragma unroll
        for (int rr = 0; rr < 2; rr++) {
            int row = warp * 2 + rr;
            float v[8];
            float sum = 0.f, ss = 0.f;
            #pragma unroll
            for (int j = 0; j < 8; j++) {
                v[j] = ys[row * CDIM + lane + 32 * j];
                sum += v[j];
                ss  += v[j] * v[j];
            }
            #pragma unroll
            for (int o = 16; o; o >>= 1) {
                sum += __shfl_xor_sync(0xffffffffu, sum, o);
                ss  += __shfl_xor_sync(0xffffffffu, ss,  o);
            }
            float mean = sum * (1.f / 256.f);
            float var  = ss * (1.f / 256.f) - mean * mean;
            float rstd = rsqrtf(var + 1e-5f);
            float* orow = out + ((size_t)tile * TILE_ROWS + row) * CDIM;
            #pragma unroll
            for (int j = 0; j < 8; j++)
                orow[lane + 32 * j] = (v[j] - mean) * rstd * gg[j] + bb[j];
        }
    }
}

// ============================================================
extern "C" void kernel_launch(void* const* d_in, const int* in_sizes, int n_in,
                              void* d_out, int out_size) {
    (void)in_sizes; (void)n_in; (void)out_size;
    const int*   user_input      = (const int*)  d_in[0];
    const float* emb             = (const float*)d_in[1];
    const int*   sc_country_idx  = (const int*)  d_in[2];
    const float* sc_country_emb  = (const float*)d_in[3];
    const int*   sc_device_idx   = (const int*)  d_in[4];
    const float* sc_device_emb   = (const float*)d_in[5];
    const int*   mf_tags_idx     = (const int*)  d_in[6];
    const float* mf_tags_emb     = (const float*)d_in[7];
    const int*   mf_history_idx  = (const int*)  d_in[8];
    const float* mf_history_emb  = (const float*)d_in[9];
    const float* fc_w            = (const float*)d_in[10];
    const float* fc_b            = (const float*)d_in[11];
    const float* ln_g            = (const float*)d_in[12];
    const float* ln_b            = (const float*)d_in[13];
    float* out = (float*)d_out;

    gather_kernel<<<B_ROWS / 8, 256>>>(
        user_input, emb,
        sc_country_idx, sc_country_emb,
        sc_device_idx,  sc_device_emb,
        mf_tags_idx,    mf_tags_emb,
        mf_history_idx, mf_history_emb);

    cudaFuncSetAttribute(gemm_ln_kernel,
                         cudaFuncAttributeMaxDynamicSharedMemorySize, SMEM_BYTES);
    gemm_ln_kernel<<<GEMM_GRID, GEMM_THREADS, SMEM_BYTES>>>(fc_w, fc_b, ln_g, ln_b, out);
}

// round 4
// speedup vs baseline: 1.4916x; 1.2577x over previous
#include <cuda_runtime.h>
#include <cuda_bf16.h>
#include <cstdint>

#define B_ROWS    16384
#define KDIM      192
#define CDIM      256

// ===================== scratch (bf16 hi/lo split of X) =====================
__device__ __nv_bfloat16 g_Xhi[B_ROWS * KDIM];
__device__ __nv_bfloat16 g_Xlo[B_ROWS * KDIM];

__device__ __forceinline__ void store_split(int idx, float x) {
    __nv_bfloat16 h = __float2bfloat16(x);
    float r = x - __bfloat162float(h);
    g_Xhi[idx] = h;
    g_Xlo[idx] = __float2bfloat16(r);
}

// ============================================================
// Kernel A: gather + mean-pool -> g_Xhi/g_Xlo  (one warp per row)
// ============================================================
__global__ void __launch_bounds__(256) gather_kernel(
    const int*   __restrict__ user_input,
    const float* __restrict__ emb,
    const int*   __restrict__ sc_country_idx,
    const float* __restrict__ sc_country_emb,
    const int*   __restrict__ sc_device_idx,
    const float* __restrict__ sc_device_emb,
    const int*   __restrict__ mf_tags_idx,
    const float* __restrict__ mf_tags_emb,
    const int*   __restrict__ mf_history_idx,
    const float* __restrict__ mf_history_emb)
{
    int row  = (blockIdx.x * blockDim.x + threadIdx.x) >> 5;
    int lane = threadIdx.x & 31;
    if (row >= B_ROWS) return;

    int u = user_input[row];
    int base = row * KDIM;

    // main embedding: 64 floats
    float2 e = ((const float2*)(emb + (size_t)u * 64))[lane];
    store_split(base + 2 * lane,     e.x);
    store_split(base + 2 * lane + 1, e.y);

    // scalar side features
    int ci = sc_country_idx[u];
    int di = sc_device_idx[u];
    store_split(base + 64 + lane, sc_country_emb[(size_t)ci * 32 + lane]);
    store_split(base + 96 + lane, sc_device_emb[(size_t)di * 32 + lane]);

    // tags: mean over 20
    int ti = (lane < 20) ? mf_tags_idx[(size_t)u * 20 + lane] : 0;
    float tacc = 0.f;
    #pragma unroll
    for (int t = 0; t < 20; t++) {
        int id = __shfl_sync(0xffffffffu, ti, t);
        tacc += mf_tags_emb[(size_t)id * 32 + lane];
    }
    store_split(base + 128 + lane, tacc * (1.f / 20.f));

    // history: mean over 50
    int hA = mf_history_idx[(size_t)u * 50 + lane];
    int hB = (lane < 18) ? mf_history_idx[(size_t)u * 50 + 32 + lane] : 0;
    float a0 = 0.f, a1 = 0.f;
    #pragma unroll
    for (int t = 0; t < 32; t++) {
        int id = __shfl_sync(0xffffffffu, hA, t);
        a0 += mf_history_emb[(size_t)id * 32 + lane];
    }
    #pragma unroll
    for (int t = 0; t < 18; t++) {
        int id = __shfl_sync(0xffffffffu, hB, t);
        a1 += mf_history_emb[(size_t)id * 32 + lane];
    }
    store_split(base + 160 + lane, (a0 + a1) * (1.f / 50.f));
}

// ============================================================
// Kernel B: HMMA (mma.sync m16n8k16 bf16) GEMM + bias/relu/LN
//   CTA: 512 thr = 16 warps (4 m-groups x 4 n-groups)
//   CTA tile: 128 rows x 256 cols, K=192 (2 smem K-halves x 3 emu passes)
// ============================================================
#define STRIDE_B  208                    // bytes per smem row (96 bf16 + pad)
#define XSZ       (128 * STRIDE_B)       // 26624
#define WSZ       (256 * STRIDE_B)       // 53248
#define OFF_WHI   (4 * XSZ)              // 106496
#define OFF_WLO   (OFF_WHI + WSZ)        // 159744
#define OFF_PAR   (OFF_WLO + WSZ)        // 212992
#define SMEM_SZ   (OFF_PAR + 3 * 256 * 4)// 216064
#define YS_STRIDE 260                    // floats; 1040B (mod128=16) conflict-free

__device__ __forceinline__ uint32_t smem_u32(const void* p) {
    uint32_t a;
    asm("{ .reg .u64 t; cvta.to.shared.u64 t, %1; cvt.u32.u64 %0, t; }"
        : "=r"(a) : "l"(p));
    return a;
}

__device__ __forceinline__ void ldsm_x4(uint32_t r[4], uint32_t addr) {
    asm volatile("ldmatrix.sync.aligned.m8n8.x4.shared.b16 {%0,%1,%2,%3}, [%4];"
        : "=r"(r[0]), "=r"(r[1]), "=r"(r[2]), "=r"(r[3]) : "r"(addr));
}

__device__ __forceinline__ void mma16816(float* d, const uint32_t* a,
                                         uint32_t b0, uint32_t b1) {
    asm volatile(
        "mma.sync.aligned.m16n8k16.row.col.f32.bf16.bf16.f32 "
        "{%0,%1,%2,%3}, {%4,%5,%6,%7}, {%8,%9}, {%0,%1,%2,%3};"
        : "+f"(d[0]), "+f"(d[1]), "+f"(d[2]), "+f"(d[3])
        : "r"(a[0]), "r"(a[1]), "r"(a[2]), "r"(a[3]), "r"(b0), "r"(b1));
}

__device__ __forceinline__ uint32_t pack_bf16(float a, float b) {
    __nv_bfloat162 t = __floats2bfloat162_rn(a, b);
    return *(uint32_t*)&t;
}

__global__ void __launch_bounds__(512, 1) gemm_ln_mma_kernel(
    const float* __restrict__ fc_w,   // [256][192]
    const float* __restrict__ fc_b,
    const float* __restrict__ ln_g,
    const float* __restrict__ ln_b,
    float*       __restrict__ out)    // [B_ROWS][256]
{
    extern __shared__ __align__(16) char smem[];
    const uint32_t sb = smem_u32(smem);
    const int tid  = threadIdx.x;
    const int lane = tid & 31;
    const int w    = tid >> 5;
    const int mgrp = w >> 2;      // 0..3 : rows mgrp*32..+31
    const int ngrp = w & 3;       // 0..3 : cols ngrp*64..+63
    const int m_base = blockIdx.x * 128;

    float* sPar = (float*)(smem + OFF_PAR);   // bias[256], g[256], b[256]

    // ---- params ----
    if (tid < 256) {
        sPar[tid]       = fc_b[tid];
        sPar[256 + tid] = ln_g[tid];
        sPar[512 + tid] = ln_b[tid];
    }

    // ---- X tiles: [half][hi/lo], 128 rows x 96 bf16, padded rows ----
    {
        const __nv_bfloat16* gp[2] = { g_Xhi, g_Xlo };
        #pragma unroll
        for (int hl = 0; hl < 2; hl++)
            #pragma unroll
            for (int half = 0; half < 2; half++) {
                char* dst = smem + (half * 2 + hl) * XSZ;
                for (int i = tid; i < 128 * 12; i += 512) {
                    int r = i / 12, q = i - r * 12;
                    const uint4* src = (const uint4*)
                        (gp[hl] + (size_t)(m_base + r) * KDIM + half * 96) + q;
                    *(uint4*)(dst + r * STRIDE_B + q * 16) = *src;
                }
            }
    }

    float acc[2][8][4];
    #pragma unroll
    for (int i = 0; i < 2; i++)
        #pragma unroll
        for (int j = 0; j < 8; j++)
            #pragma unroll
            for (int k = 0; k < 4; k++) acc[i][j][k] = 0.f;

    const int rk   = lane & 15;                 // ldmatrix row within 16
    const uint32_t kbyte = (uint32_t)((lane >> 4) << 4);   // k-half offset bytes

    #pragma unroll
    for (int half = 0; half < 2; half++) {
        // load + convert W K-half (fp32 -> bf16 hi/lo)
        for (int i = tid; i < 256 * 24; i += 512) {
            int n = i / 24, q = i - n * 24;
            float4 wv = *(const float4*)(fc_w + (size_t)n * KDIM + half * 96 + q * 4);
            __nv_bfloat16 h0 = __float2bfloat16(wv.x);
            __nv_bfloat16 h1 = __float2bfloat16(wv.y);
            __nv_bfloat16 h2 = __float2bfloat16(wv.z);
            __nv_bfloat16 h3 = __float2bfloat16(wv.w);
            uint2 hi, lo;
            hi.x = pack_bf16(__bfloat162float(h0), __bfloat162float(h1));
            hi.y = pack_bf16(__bfloat162float(h2), __bfloat162float(h3));
            lo.x = pack_bf16(wv.x - __bfloat162float(h0), wv.y - __bfloat162float(h1));
            lo.y = pack_bf16(wv.z - __bfloat162float(h2), wv.w - __bfloat162float(h3));
            *(uint2*)(smem + OFF_WHI + n * STRIDE_B + q * 8) = hi;
            *(uint2*)(smem + OFF_WLO + n * STRIDE_B + q * 8) = lo;
        }
        __syncthreads();

        const uint32_t xoff[3] = { (uint32_t)(half * 2 + 0) * XSZ,
                                   (uint32_t)(half * 2 + 0) * XSZ,
                                   (uint32_t)(half * 2 + 1) * XSZ };
        const uint32_t woff[3] = { OFF_WHI, OFF_WLO, OFF_WHI };

        #pragma unroll
        for (int pass = 0; pass < 3; pass++) {
            uint32_t xb = sb + xoff[pass] + (mgrp * 32 + rk) * STRIDE_B + kbyte;
            uint32_t wb = sb + woff[pass] + (ngrp * 64 + rk) * STRIDE_B + kbyte;
            #pragma unroll
            for (int s = 0; s < 6; s++) {
                uint32_t ko = (uint32_t)s * 32;   // 16 bf16 = 32 bytes
                uint32_t a0[4], a1[4], bb[4][4];
                ldsm_x4(a0, xb + ko);
                ldsm_x4(a1, xb + 16 * STRIDE_B + ko);
                #pragma unroll
                for (int j = 0; j < 4; j++)
                    ldsm_x4(bb[j], wb + j * 16 * STRIDE_B + ko);
                #pragma unroll
                for (int j = 0; j < 4; j++) {
                    mma16816(acc[0][2*j],     a0, bb[j][0], bb[j][2]);
                    mma16816(acc[0][2*j + 1], a0, bb[j][1], bb[j][3]);
                    mma16816(acc[1][2*j],     a1, bb[j][0], bb[j][2]);
                    mma16816(acc[1][2*j + 1], a1, bb[j][1], bb[j][3]);
                }
            }
        }
        __syncthreads();   // done reading this W half (and X before ys overwrite)
    }

    // ---- epilogue: fragments -> ys smem (bias+relu) ----
    float* ys = (float*)smem;   // [128][YS_STRIDE]
    {
        const int r0 = mgrp * 32 + (lane >> 2);
        const int c0 = ngrp * 64 + (lane & 3) * 2;
        #pragma unroll
        for (int mf = 0; mf < 2; mf++)
            #pragma unroll
            for (int nf = 0; nf < 8; nf++) {
                int r = r0 + mf * 16;
                int c = c0 + nf * 8;
                float b0 = sPar[c], b1 = sPar[c + 1];
                float2 v0 = make_float2(fmaxf(acc[mf][nf][0] + b0, 0.f),
                                        fmaxf(acc[mf][nf][1] + b1, 0.f));
                float2 v1 = make_float2(fmaxf(acc[mf][nf][2] + b0, 0.f),
                                        fmaxf(acc[mf][nf][3] + b1, 0.f));
                *(float2*)&ys[r * YS_STRIDE + c]       = v0;
                *(float2*)&ys[(r + 8) * YS_STRIDE + c] = v1;
            }
    }
    __syncthreads();

    // ---- LayerNorm: warp w handles rows w*8 .. w*8+7 ----
    #pragma unroll
    for (int rr = 0; rr < 8; rr++) {
        int r = w * 8 + rr;
        float v[8];
        float sum = 0.f, ss = 0.f;
        #pragma unroll
        for (int j = 0; j < 8; j++) {
            v[j] = ys[r * YS_STRIDE + lane + 32 * j];
            sum += v[j];
            ss  += v[j] * v[j];
        }
        #pragma unroll
        for (int o = 16; o; o >>= 1) {
            sum += __shfl_xor_sync(0xffffffffu, sum, o);
            ss  += __shfl_xor_sync(0xffffffffu, ss,  o);
        }
        float mean = sum * (1.f / 256.f);
        float var  = ss * (1.f / 256.f) - mean * mean;
        float rstd = rsqrtf(var + 1e-5f);
        float* orow = out + (size_t)(m_base + r) * CDIM;
        #pragma unroll
        for (int j = 0; j < 8; j++) {
            int c = lane + 32 * j;
            orow[c] = (v[j] - mean) * rstd * sPar[256 + c] + sPar[512 + c];
        }
    }
}

// ============================================================
extern "C" void kernel_launch(void* const* d_in, const int* in_sizes, int n_in,
                              void* d_out, int out_size) {
    (void)in_sizes; (void)n_in; (void)out_size;
    const int*   user_input      = (const int*)  d_in[0];
    const float* emb             = (const float*)d_in[1];
    const int*   sc_country_idx  = (const int*)  d_in[2];
    const float* sc_country_emb  = (const float*)d_in[3];
    const int*   sc_device_idx   = (const int*)  d_in[4];
    const float* sc_device_emb   = (const float*)d_in[5];
    const int*   mf_tags_idx     = (const int*)  d_in[6];
    const float* mf_tags_emb     = (const float*)d_in[7];
    const int*   mf_history_idx  = (const int*)  d_in[8];
    const float* mf_history_emb  = (const float*)d_in[9];
    const float* fc_w            = (const float*)d_in[10];
    const float* fc_b            = (const float*)d_in[11];
    const float* ln_g            = (const float*)d_in[12];
    const float* ln_b            = (const float*)d_in[13];
    float* out = (float*)d_out;

    gather_kernel<<<B_ROWS / 8, 256>>>(
        user_input, emb,
        sc_country_idx, sc_country_emb,
        sc_device_idx,  sc_device_emb,
        mf_tags_idx,    mf_tags_emb,
        mf_history_idx, mf_history_emb);

    cudaFuncSetAttribute(gemm_ln_mma_kernel,
                         cudaFuncAttributeMaxDynamicSharedMemorySize, SMEM_SZ);
    gemm_ln_mma_kernel<<<B_ROWS / 128, 512, SMEM_SZ>>>(fc_w, fc_b, ln_g, ln_b, out);
}